// round 5
// baseline (speedup 1.0000x reference)
#include <cuda_runtime.h>
#include <math.h>

#define NB   128
#define NHID 512
#define GATE_ELEMS (NB * NHID)   // 65536
#define NSPLIT 8
#define GEMM2_BLOCKS 16          // 8 j-tiles * 2 m-tiles (paired p/o, full-K)
#define TRACE_BLOCKS 32768

// ---------------- device scratch (no allocations allowed) ----------------
__device__ float d_part[NSPLIT][NB * 1024];  // split-K partials, 4 MB
__device__ float d_av  [GATE_ELEMS];         // 1 - g
__device__ float d_cgv [GATE_ELEMS];         // dg * delta_h
__device__ float d_crv [GATE_ELEMS];         // dr * g
__device__ float d_hv  [GATE_ELEMS];         // new h
__device__ int   d_cnt [256];                // per-block open counts (k_gates grid)

// ---------------------------------------------------------------------------
// Launch 1: split-K dual GEMM for g/r pre-activations.
//   CTA tile 128m x 64n, BK=16, 256 threads, 8x4 register tile,
//   double-buffered smem (one sync per k-tile). grid = (16 n-tiles, 8 splits).
//   split s: half = s>>2 picks x/h operands, kb = (s&3)*128 in that half.
// ---------------------------------------------------------------------------
__global__ void __launch_bounds__(256) k_gemm1(
    const float* __restrict__ x, const float* __restrict__ h_last,
    const float* __restrict__ w_gx, const float* __restrict__ w_gh,
    const float* __restrict__ w_rx, const float* __restrict__ w_rh)
{
    __shared__ float As[2 * 16 * 132];   // [stage][k][m(128)+pad]
    __shared__ float Ws[2 * 16 * 68];    // [stage][k][n(64)+pad]

    const int tid = threadIdx.x;
    const int n0  = blockIdx.x * 64;     // n in [0,1024)
    const int s   = blockIdx.y;          // split 0..7
    const int half = s >> 2;             // 0: x-part, 1: h-part
    const int kb   = (s & 3) * 128;      // offset within the 512-wide half

    const bool g2 = (n0 >= 512);
    const int  j0 = g2 ? (n0 - 512) : n0;
    const float* A = half ? h_last : x;
    const float* W = g2 ? (half ? w_rh : w_rx) : (half ? w_gh : w_gx);
    float* outp    = d_part[s];

    // A loader: 128 rows x 16 k = 512 float4; 2 per thread (k offsets ca, ca+8)
    const int lmA = tid & 127;
    const int ca  = (tid >> 7) << 2;     // 0 or 4
    // W loader: 64 rows x 16 k = 256 float4; 1 per thread
    const int lnW = tid & 63;
    const int cw  = (tid >> 6) << 2;     // 0,4,8,12

    const int tx = tid & 15;             // n-dir (4 cols each)
    const int ty = tid >> 4;             // m-dir (8 rows each)

    const float* Aload = A + lmA * 512 + kb;
    const float* Wload = W + (j0 + lnW) * 512 + kb;

    float acc[8][4];
    #pragma unroll
    for (int i = 0; i < 8; i++)
        #pragma unroll
        for (int j = 0; j < 4; j++) acc[i][j] = 0.f;

    float4 av0 = *(const float4*)(Aload + ca);
    float4 av1 = *(const float4*)(Aload + ca + 8);
    float4 wv  = *(const float4*)(Wload + cw);

    // store stage 0
    As[(ca + 0) * 132 + lmA] = av0.x; As[(ca + 1) * 132 + lmA] = av0.y;
    As[(ca + 2) * 132 + lmA] = av0.z; As[(ca + 3) * 132 + lmA] = av0.w;
    As[(ca + 8) * 132 + lmA] = av1.x; As[(ca + 9) * 132 + lmA] = av1.y;
    As[(ca +10) * 132 + lmA] = av1.z; As[(ca +11) * 132 + lmA] = av1.w;
    Ws[(cw + 0) * 68 + lnW] = wv.x; Ws[(cw + 1) * 68 + lnW] = wv.y;
    Ws[(cw + 2) * 68 + lnW] = wv.z; Ws[(cw + 3) * 68 + lnW] = wv.w;
    __syncthreads();

    #pragma unroll 1
    for (int t = 0; t < 8; t++) {
        const int cur = t & 1;
        const float* as = As + cur * (16 * 132);
        const float* ws = Ws + cur * (16 * 68);

        if (t < 7) {                      // prefetch next k-tile to registers
            const int ko = (t + 1) * 16;
            av0 = *(const float4*)(Aload + ko + ca);
            av1 = *(const float4*)(Aload + ko + ca + 8);
            wv  = *(const float4*)(Wload + ko + cw);
        }

        #pragma unroll
        for (int kk = 0; kk < 16; kk++) {
            const float4 a0 = *(const float4*)(as + kk * 132 + (ty << 3));
            const float4 a1 = *(const float4*)(as + kk * 132 + (ty << 3) + 4);
            const float4 w  = *(const float4*)(ws + kk * 68 + (tx << 2));
            acc[0][0]=fmaf(a0.x,w.x,acc[0][0]); acc[0][1]=fmaf(a0.x,w.y,acc[0][1]);
            acc[0][2]=fmaf(a0.x,w.z,acc[0][2]); acc[0][3]=fmaf(a0.x,w.w,acc[0][3]);
            acc[1][0]=fmaf(a0.y,w.x,acc[1][0]); acc[1][1]=fmaf(a0.y,w.y,acc[1][1]);
            acc[1][2]=fmaf(a0.y,w.z,acc[1][2]); acc[1][3]=fmaf(a0.y,w.w,acc[1][3]);
            acc[2][0]=fmaf(a0.z,w.x,acc[2][0]); acc[2][1]=fmaf(a0.z,w.y,acc[2][1]);
            acc[2][2]=fmaf(a0.z,w.z,acc[2][2]); acc[2][3]=fmaf(a0.z,w.w,acc[2][3]);
            acc[3][0]=fmaf(a0.w,w.x,acc[3][0]); acc[3][1]=fmaf(a0.w,w.y,acc[3][1]);
            acc[3][2]=fmaf(a0.w,w.z,acc[3][2]); acc[3][3]=fmaf(a0.w,w.w,acc[3][3]);
            acc[4][0]=fmaf(a1.x,w.x,acc[4][0]); acc[4][1]=fmaf(a1.x,w.y,acc[4][1]);
            acc[4][2]=fmaf(a1.x,w.z,acc[4][2]); acc[4][3]=fmaf(a1.x,w.w,acc[4][3]);
            acc[5][0]=fmaf(a1.y,w.x,acc[5][0]); acc[5][1]=fmaf(a1.y,w.y,acc[5][1]);
            acc[5][2]=fmaf(a1.y,w.z,acc[5][2]); acc[5][3]=fmaf(a1.y,w.w,acc[5][3]);
            acc[6][0]=fmaf(a1.z,w.x,acc[6][0]); acc[6][1]=fmaf(a1.z,w.y,acc[6][1]);
            acc[6][2]=fmaf(a1.z,w.z,acc[6][2]); acc[6][3]=fmaf(a1.z,w.w,acc[6][3]);
            acc[7][0]=fmaf(a1.w,w.x,acc[7][0]); acc[7][1]=fmaf(a1.w,w.y,acc[7][1]);
            acc[7][2]=fmaf(a1.w,w.z,acc[7][2]); acc[7][3]=fmaf(a1.w,w.w,acc[7][3]);
        }

        if (t < 7) {
            float* asn = As + (cur ^ 1) * (16 * 132);
            float* wsn = Ws + (cur ^ 1) * (16 * 68);
            asn[(ca + 0) * 132 + lmA] = av0.x; asn[(ca + 1) * 132 + lmA] = av0.y;
            asn[(ca + 2) * 132 + lmA] = av0.z; asn[(ca + 3) * 132 + lmA] = av0.w;
            asn[(ca + 8) * 132 + lmA] = av1.x; asn[(ca + 9) * 132 + lmA] = av1.y;
            asn[(ca +10) * 132 + lmA] = av1.z; asn[(ca +11) * 132 + lmA] = av1.w;
            wsn[(cw + 0) * 68 + lnW] = wv.x; wsn[(cw + 1) * 68 + lnW] = wv.y;
            wsn[(cw + 2) * 68 + lnW] = wv.z; wsn[(cw + 3) * 68 + lnW] = wv.w;
            __syncthreads();
        }
    }

    #pragma unroll
    for (int i = 0; i < 8; i++) {
        float4 v = make_float4(acc[i][0], acc[i][1], acc[i][2], acc[i][3]);
        *(float4*)(outp + ((ty << 3) + i) * 1024 + n0 + (tx << 2)) = v;
    }
}

// ---------------------------------------------------------------------------
// Launch 2: gate epilogue — sum partials + bias, gate math, coefficients,
// e_b updates, per-block open counts. grid=256
// ---------------------------------------------------------------------------
__global__ void __launch_bounds__(256) k_gates(
    const float* __restrict__ h_last,
    const float* __restrict__ b_g, const float* __restrict__ b_r,
    const float* __restrict__ e_b_g, const float* __restrict__ e_b_r,
    float* __restrict__ out_h, float* __restrict__ out_ebg, float* __restrict__ out_ebr)
{
    __shared__ int scnt[8];
    const int idx = blockIdx.x * 256 + threadIdx.x;   // b*512 + j
    const int b = idx >> 9;
    const int j = idx & 511;
    const int og  = b * 1024 + j;
    const int orr = og + 512;

    float gpre = b_g[j], rpre = b_r[j];
    #pragma unroll
    for (int s = 0; s < NSPLIT; s++) {
        gpre += d_part[s][og];
        rpre += d_part[s][orr];
    }

    float g = tanhf(gpre);
    g = fmaxf(g, 0.f);                      // relu(tanh)
    const float r  = tanhf(rpre);
    const float hl = h_last[idx];
    const float h  = g * r + (1.f - g) * hl;
    const float Hg = (g > 0.f) ? 1.f : 0.f;
    const float dg = (1.f - g * g) * Hg;
    const float dr = 1.f - r * r;
    const float delta = r - hl;
    const float a  = 1.f - g;
    const float cg = dg * delta;
    const float cr = dr * g;

    d_av[idx]  = a;
    d_cgv[idx] = cg;
    d_crv[idx] = cr;
    d_hv[idx]  = h;

    out_h[idx]   = h;
    out_ebg[idx] = e_b_g[idx] * a + cg;
    out_ebr[idx] = e_b_r[idx] * a + cr;

    const int cnt = __popc(__ballot_sync(0xffffffffu, g > 0.f));
    if ((threadIdx.x & 31) == 0) scnt[threadIdx.x >> 5] = cnt;
    __syncthreads();
    if (threadIdx.x == 0) {
        int t = 0;
        #pragma unroll
        for (int w = 0; w < 8; w++) t += scnt[w];
        d_cnt[blockIdx.x] = t;
    }
}

// ---------------------------------------------------------------------------
// Paired full-K GEMM for p & o with fused activation epilogue (hidden under
// the trace stream inside k_fused, so plain 4x4 tiles are fine).
// ---------------------------------------------------------------------------
__device__ __forceinline__ void gemm2_body(
    const float* __restrict__ x,
    const float* __restrict__ w_px, const float* __restrict__ w_ph,
    const float* __restrict__ w_ox, const float* __restrict__ w_oh,
    const float* __restrict__ b_p,  const float* __restrict__ b_o,
    float* __restrict__ out, int bx, int tid)
{
    __shared__ float As[16][68];
    __shared__ float Ps[16][68];
    __shared__ float Os[16][68];

    const int j0 = (bx & 7) * 64;
    const int m0 = (bx >> 3) * 64;

    const int lm  = tid & 63;
    const int lk4 = (tid >> 6) << 2;
    const int tx  = tid & 15;
    const int ty  = tid >> 4;

    float accP[4][4], accO[4][4];
    #pragma unroll
    for (int i = 0; i < 4; i++)
        #pragma unroll
        for (int j = 0; j < 4; j++) { accP[i][j] = 0.f; accO[i][j] = 0.f; }

    float4 av = *(const float4*)(x    + (m0 + lm) * 512 + lk4);
    float4 pv = *(const float4*)(w_px + (j0 + lm) * 512 + lk4);
    float4 ov = *(const float4*)(w_ox + (j0 + lm) * 512 + lk4);

    for (int kt = 0; kt < 1024; kt += 16) {
        __syncthreads();
        As[lk4 + 0][lm] = av.x; As[lk4 + 1][lm] = av.y;
        As[lk4 + 2][lm] = av.z; As[lk4 + 3][lm] = av.w;
        Ps[lk4 + 0][lm] = pv.x; Ps[lk4 + 1][lm] = pv.y;
        Ps[lk4 + 2][lm] = pv.z; Ps[lk4 + 3][lm] = pv.w;
        Os[lk4 + 0][lm] = ov.x; Os[lk4 + 1][lm] = ov.y;
        Os[lk4 + 2][lm] = ov.z; Os[lk4 + 3][lm] = ov.w;
        __syncthreads();

        const int kn = kt + 16;
        if (kn < 1024) {
            const int kk2 = (kn < 512) ? kn : (kn - 512);
            const float* An = (kn < 512) ? x    : d_hv;
            const float* Pn = (kn < 512) ? w_px : w_ph;
            const float* On = (kn < 512) ? w_ox : w_oh;
            av = *(const float4*)(An + (m0 + lm) * 512 + kk2 + lk4);
            pv = *(const float4*)(Pn + (j0 + lm) * 512 + kk2 + lk4);
            ov = *(const float4*)(On + (j0 + lm) * 512 + kk2 + lk4);
        }

        #pragma unroll
        for (int kk = 0; kk < 16; kk++) {
            const float4 a = *(const float4*)&As[kk][ty << 2];
            const float4 p = *(const float4*)&Ps[kk][tx << 2];
            const float4 o = *(const float4*)&Os[kk][tx << 2];
            accP[0][0]=fmaf(a.x,p.x,accP[0][0]); accP[0][1]=fmaf(a.x,p.y,accP[0][1]);
            accP[0][2]=fmaf(a.x,p.z,accP[0][2]); accP[0][3]=fmaf(a.x,p.w,accP[0][3]);
            accP[1][0]=fmaf(a.y,p.x,accP[1][0]); accP[1][1]=fmaf(a.y,p.y,accP[1][1]);
            accP[1][2]=fmaf(a.y,p.z,accP[1][2]); accP[1][3]=fmaf(a.y,p.w,accP[1][3]);
            accP[2][0]=fmaf(a.z,p.x,accP[2][0]); accP[2][1]=fmaf(a.z,p.y,accP[2][1]);
            accP[2][2]=fmaf(a.z,p.z,accP[2][2]); accP[2][3]=fmaf(a.z,p.w,accP[2][3]);
            accP[3][0]=fmaf(a.w,p.x,accP[3][0]); accP[3][1]=fmaf(a.w,p.y,accP[3][1]);
            accP[3][2]=fmaf(a.w,p.z,accP[3][2]); accP[3][3]=fmaf(a.w,p.w,accP[3][3]);
            accO[0][0]=fmaf(a.x,o.x,accO[0][0]); accO[0][1]=fmaf(a.x,o.y,accO[0][1]);
            accO[0][2]=fmaf(a.x,o.z,accO[0][2]); accO[0][3]=fmaf(a.x,o.w,accO[0][3]);
            accO[1][0]=fmaf(a.y,o.x,accO[1][0]); accO[1][1]=fmaf(a.y,o.y,accO[1][1]);
            accO[1][2]=fmaf(a.y,o.z,accO[1][2]); accO[1][3]=fmaf(a.y,o.w,accO[1][3]);
            accO[2][0]=fmaf(a.z,o.x,accO[2][0]); accO[2][1]=fmaf(a.z,o.y,accO[2][1]);
            accO[2][2]=fmaf(a.z,o.z,accO[2][2]); accO[2][3]=fmaf(a.z,o.w,accO[2][3]);
            accO[3][0]=fmaf(a.w,o.x,accO[3][0]); accO[3][1]=fmaf(a.w,o.y,accO[3][1]);
            accO[3][2]=fmaf(a.w,o.z,accO[3][2]); accO[3][3]=fmaf(a.w,o.w,accO[3][3]);
        }
    }

    #pragma unroll
    for (int i = 0; i < 4; i++) {
        float4 v;
        #pragma unroll
        for (int j = 0; j < 4; j++) {
            const int jj = j0 + (tx << 2) + j;
            const float pre_p = accP[i][j] + b_p[jj];
            const float pre_o = accO[i][j] + b_o[jj];
            const float pval  = tanhf(pre_p);
            const float oval  = 1.f / (1.f + expf(-pre_o));
            ((float*)&v)[j] = oval * pval;
        }
        *(float4*)(out + (m0 + (ty << 2) + i) * 512 + j0 + (tx << 2)) = v;
    }
}

// Trace row update: streaming loads/stores (zero reuse on the 1 GB stream).
__device__ __forceinline__ void trace_body(
    int idx,
    const float* __restrict__ x,  const float* __restrict__ hl,
    const float* __restrict__ egx, const float* __restrict__ egh,
    const float* __restrict__ erx, const float* __restrict__ erh,
    float* __restrict__ ogx, float* __restrict__ ogh,
    float* __restrict__ orx, float* __restrict__ orh)
{
    const int i   = (idx & 127) << 2;
    const int bj  = idx >> 7;
    const int b   = bj >> 9;

    const float a  = __ldg(&d_av[bj]);
    const float cg = __ldg(&d_cgv[bj]);
    const float cr = __ldg(&d_crv[bj]);

    const float4 xv = __ldg((const float4*)(x  + (b << 9) + i));
    const float4 hv = __ldg((const float4*)(hl + (b << 9) + i));
    const int off = (bj << 9) + i;

    float4 e, t;

    e = __ldcs((const float4*)(egx + off));
    t.x = e.x * a + cg * xv.x; t.y = e.y * a + cg * xv.y;
    t.z = e.z * a + cg * xv.z; t.w = e.w * a + cg * xv.w;
    __stcs((float4*)(ogx + off), t);

    e = __ldcs((const float4*)(egh + off));
    t.x = e.x * a + cg * hv.x; t.y = e.y * a + cg * hv.y;
    t.z = e.z * a + cg * hv.z; t.w = e.w * a + cg * hv.w;
    __stcs((float4*)(ogh + off), t);

    e = __ldcs((const float4*)(erx + off));
    t.x = e.x * a + cr * xv.x; t.y = e.y * a + cr * xv.y;
    t.z = e.z * a + cr * xv.z; t.w = e.w * a + cr * xv.w;
    __stcs((float4*)(orx + off), t);

    e = __ldcs((const float4*)(erh + off));
    t.x = e.x * a + cr * hv.x; t.y = e.y * a + cr * hv.y;
    t.z = e.z * a + cr * hv.z; t.w = e.w * a + cr * hv.w;
    __stcs((float4*)(orh + off), t);
}

// ---------------------------------------------------------------------------
// Launch 3: FUSED kernel.
//   blocks [0, 16)        : paired p/o GEMM, fused activation -> out
//   blocks [16, 16+32768) : HBM-bound trace update
//   block  16+32768       : openings scalar from d_cnt
// ---------------------------------------------------------------------------
__global__ void __launch_bounds__(256) k_fused(
    const float* __restrict__ x,  const float* __restrict__ h_last,
    const float* __restrict__ w_px, const float* __restrict__ w_ph,
    const float* __restrict__ w_ox, const float* __restrict__ w_oh,
    const float* __restrict__ b_p,  const float* __restrict__ b_o,
    const float* __restrict__ egx, const float* __restrict__ egh,
    const float* __restrict__ erx, const float* __restrict__ erh,
    float* __restrict__ ogx, float* __restrict__ ogh,
    float* __restrict__ orx, float* __restrict__ orh,
    float* __restrict__ o_out, float* __restrict__ o_open)
{
    const int bx = blockIdx.x;
    if (bx < GEMM2_BLOCKS) {
        gemm2_body(x, w_px, w_ph, w_ox, w_oh, b_p, b_o, o_out, bx, threadIdx.x);
    } else if (bx < GEMM2_BLOCKS + TRACE_BLOCKS) {
        const int idx = (bx - GEMM2_BLOCKS) * 256 + threadIdx.x;
        trace_body(idx, x, h_last, egx, egh, erx, erh, ogx, ogh, orx, orh);
    } else {
        __shared__ int scnt[256];
        scnt[threadIdx.x] = d_cnt[threadIdx.x];
        __syncthreads();
        for (int st = 128; st > 0; st >>= 1) {
            if (threadIdx.x < st) scnt[threadIdx.x] += scnt[threadIdx.x + st];
            __syncthreads();
        }
        if (threadIdx.x == 0)
            o_open[0] = (float)scnt[0] * (1.f / (float)GATE_ELEMS);
    }
}

// ---------------------------------------------------------------------------
extern "C" void kernel_launch(void* const* d_in, const int* in_sizes, int n_in,
                              void* d_out, int out_size)
{
    const float* x      = (const float*)d_in[0];
    const float* h_last = (const float*)d_in[1];
    const float* w_gx   = (const float*)d_in[2];
    const float* w_gh   = (const float*)d_in[3];
    const float* b_g    = (const float*)d_in[4];
    const float* w_rx   = (const float*)d_in[5];
    const float* w_rh   = (const float*)d_in[6];
    const float* b_r    = (const float*)d_in[7];
    const float* w_px   = (const float*)d_in[8];
    const float* w_ph   = (const float*)d_in[9];
    const float* b_p    = (const float*)d_in[10];
    const float* w_ox   = (const float*)d_in[11];
    const float* w_oh   = (const float*)d_in[12];
    const float* b_o    = (const float*)d_in[13];
    const float* e_w_gx = (const float*)d_in[14];
    const float* e_w_gh = (const float*)d_in[15];
    const float* e_b_g  = (const float*)d_in[16];
    const float* e_w_rx = (const float*)d_in[17];
    const float* e_w_rh = (const float*)d_in[18];
    const float* e_b_r  = (const float*)d_in[19];

    float* out    = (float*)d_out;
    float* o_out  = out;                  // (128,512)
    float* o_h    = out + 65536;          // (128,512)
    float* o_egx  = out + 131072;         // (128,512,512)
    float* o_egh  = out + 33685504;       // (128,512,512)
    float* o_ebg  = out + 67239936;       // (128,512)
    float* o_erx  = out + 67305472;       // (128,512,512)
    float* o_erh  = out + 100859904;      // (128,512,512)
    float* o_ebr  = out + 134414336;      // (128,512)
    float* o_open = out + 134479872;      // scalar

    // g/r pre-activations: 128x64 CTA tiles, split-K=8 -> 128 CTAs
    k_gemm1<<<dim3(16, NSPLIT), 256>>>(x, h_last, w_gx, w_gh, w_rx, w_rh);

    // gate math, h, e_b updates, per-block open counts
    k_gates<<<256, 256>>>(h_last, b_g, b_r, e_b_g, e_b_r, o_h, o_ebg, o_ebr);

    // fused: paired p/o GEMM (+activations) + trace streamer + openings
    k_fused<<<GEMM2_BLOCKS + TRACE_BLOCKS + 1, 256>>>(
        x, h_last, w_px, w_ph, w_ox, w_oh, b_p, b_o,
        e_w_gx, e_w_gh, e_w_rx, e_w_rh,
        o_egx, o_egh, o_erx, o_erh,
        o_out, o_open);
}

// round 6
// speedup vs baseline: 1.3873x; 1.3873x over previous
#include <cuda_runtime.h>
#include <math.h>

#define NB   128
#define NHID 512
#define GATE_ELEMS (NB * NHID)   // 65536
#define NSPLIT 16
#define GEMM2_BLOCKS 16          // 8 j-tiles * 2 m-tiles (paired p/o, full-K)
#define TRACE_BLOCKS 32768

// ---------------- device scratch (no allocations allowed) ----------------
__device__ float d_part[NSPLIT][NB * 1024];  // split-K partials, 8 MB
__device__ float d_av  [GATE_ELEMS];         // 1 - g
__device__ float d_cgv [GATE_ELEMS];         // dg * delta_h
__device__ float d_crv [GATE_ELEMS];         // dr * g
__device__ float d_hv  [GATE_ELEMS];         // new h
__device__ int   d_cnt [256];                // per-block open counts (k_gates grid)

// ---------------------------------------------------------------------------
// Launch 1: split-K dual GEMM for g/r pre-activations.
//   CTA tile 128m x 128n, BK=16, 256 threads, 8x8 register tile (1 B smem per
//   FMA -> crossbar/FFMA balanced), double-buffered smem, one sync per k-tile.
//   grid = (8 n-tiles, 16 splits) = 128 CTAs. split s: half=s>>3, kb=(s&7)*64.
// ---------------------------------------------------------------------------
__global__ void __launch_bounds__(256) k_gemm1(
    const float* __restrict__ x, const float* __restrict__ h_last,
    const float* __restrict__ w_gx, const float* __restrict__ w_gh,
    const float* __restrict__ w_rx, const float* __restrict__ w_rh)
{
    __shared__ float As[2][16 * 132];   // [stage][k][m(128)+pad]
    __shared__ float Ws[2][16 * 132];   // [stage][k][n(128)+pad]

    const int tid  = threadIdx.x;
    const int n0   = blockIdx.x * 128;   // n in [0,1024)
    const int s    = blockIdx.y;         // split 0..15
    const int half = s >> 3;             // 0: x-part, 1: h-part
    const int kb   = (s & 7) * 64;       // offset within the 512-wide half

    const bool g2 = (n0 >= 512);
    const int  j0 = g2 ? (n0 - 512) : n0;
    const float* A = half ? h_last : x;
    const float* W = g2 ? (half ? w_rh : w_rx) : (half ? w_gh : w_gx);
    float* outp    = d_part[s];

    // loaders: 128 rows x 16 k per tile = 512 float4; 2 float4 per thread
    const int lr = tid & 127;            // row (m for A, n for W)
    const int ka = (tid >> 7) << 3;      // k offset: 0 or 8 (two float4 each)

    const int tx = tid & 15;             // n-dir (8 cols)
    const int ty = tid >> 4;             // m-dir (8 rows)

    const float* Aload = A + lr * 512 + kb + ka;
    const float* Wload = W + (j0 + lr) * 512 + kb + ka;

    float acc[8][8];
    #pragma unroll
    for (int i = 0; i < 8; i++)
        #pragma unroll
        for (int j = 0; j < 8; j++) acc[i][j] = 0.f;

    float4 a0 = *(const float4*)(Aload);
    float4 a1 = *(const float4*)(Aload + 4);
    float4 w0 = *(const float4*)(Wload);
    float4 w1 = *(const float4*)(Wload + 4);

    // store stage 0 (transposed [k][row])
    {
        float* as = As[0]; float* ws = Ws[0];
        as[(ka+0)*132+lr]=a0.x; as[(ka+1)*132+lr]=a0.y; as[(ka+2)*132+lr]=a0.z; as[(ka+3)*132+lr]=a0.w;
        as[(ka+4)*132+lr]=a1.x; as[(ka+5)*132+lr]=a1.y; as[(ka+6)*132+lr]=a1.z; as[(ka+7)*132+lr]=a1.w;
        ws[(ka+0)*132+lr]=w0.x; ws[(ka+1)*132+lr]=w0.y; ws[(ka+2)*132+lr]=w0.z; ws[(ka+3)*132+lr]=w0.w;
        ws[(ka+4)*132+lr]=w1.x; ws[(ka+5)*132+lr]=w1.y; ws[(ka+6)*132+lr]=w1.z; ws[(ka+7)*132+lr]=w1.w;
    }
    __syncthreads();

    #pragma unroll 1
    for (int t = 0; t < 4; t++) {        // 4 k-tiles of 16 (k-chunk = 64)
        const int cur = t & 1;
        const float* as = As[cur];
        const float* ws = Ws[cur];

        if (t < 3) {                      // prefetch next k-tile to registers
            const int ko = (t + 1) * 16;
            a0 = *(const float4*)(Aload + ko);
            a1 = *(const float4*)(Aload + ko + 4);
            w0 = *(const float4*)(Wload + ko);
            w1 = *(const float4*)(Wload + ko + 4);
        }

        #pragma unroll
        for (int kk = 0; kk < 16; kk++) {
            float a[8], w[8];
            *(float4*)&a[0] = *(const float4*)(as + kk * 132 + (ty << 3));
            *(float4*)&a[4] = *(const float4*)(as + kk * 132 + (ty << 3) + 4);
            *(float4*)&w[0] = *(const float4*)(ws + kk * 132 + (tx << 3));
            *(float4*)&w[4] = *(const float4*)(ws + kk * 132 + (tx << 3) + 4);
            #pragma unroll
            for (int i = 0; i < 8; i++)
                #pragma unroll
                for (int j = 0; j < 8; j++)
                    acc[i][j] = fmaf(a[i], w[j], acc[i][j]);
        }

        if (t < 3) {
            float* asn = As[cur ^ 1]; float* wsn = Ws[cur ^ 1];
            asn[(ka+0)*132+lr]=a0.x; asn[(ka+1)*132+lr]=a0.y; asn[(ka+2)*132+lr]=a0.z; asn[(ka+3)*132+lr]=a0.w;
            asn[(ka+4)*132+lr]=a1.x; asn[(ka+5)*132+lr]=a1.y; asn[(ka+6)*132+lr]=a1.z; asn[(ka+7)*132+lr]=a1.w;
            wsn[(ka+0)*132+lr]=w0.x; wsn[(ka+1)*132+lr]=w0.y; wsn[(ka+2)*132+lr]=w0.z; wsn[(ka+3)*132+lr]=w0.w;
            wsn[(ka+4)*132+lr]=w1.x; wsn[(ka+5)*132+lr]=w1.y; wsn[(ka+6)*132+lr]=w1.z; wsn[(ka+7)*132+lr]=w1.w;
            __syncthreads();
        }
    }

    #pragma unroll
    for (int i = 0; i < 8; i++) {
        const int row = (ty << 3) + i;
        *(float4*)(outp + row * 1024 + n0 + (tx << 3)) =
            make_float4(acc[i][0], acc[i][1], acc[i][2], acc[i][3]);
        *(float4*)(outp + row * 1024 + n0 + (tx << 3) + 4) =
            make_float4(acc[i][4], acc[i][5], acc[i][6], acc[i][7]);
    }
}

// ---------------------------------------------------------------------------
// Launch 2: gate epilogue — sum partials + bias, gate math, coefficients,
// e_b updates, per-block open counts. grid=256
// ---------------------------------------------------------------------------
__global__ void __launch_bounds__(256) k_gates(
    const float* __restrict__ h_last,
    const float* __restrict__ b_g, const float* __restrict__ b_r,
    const float* __restrict__ e_b_g, const float* __restrict__ e_b_r,
    float* __restrict__ out_h, float* __restrict__ out_ebg, float* __restrict__ out_ebr)
{
    __shared__ int scnt[8];
    const int idx = blockIdx.x * 256 + threadIdx.x;   // b*512 + j
    const int b = idx >> 9;
    const int j = idx & 511;
    const int og  = b * 1024 + j;
    const int orr = og + 512;

    float gpre = b_g[j], rpre = b_r[j];
    #pragma unroll
    for (int s = 0; s < NSPLIT; s++) {
        gpre += d_part[s][og];
        rpre += d_part[s][orr];
    }

    float g = tanhf(gpre);
    g = fmaxf(g, 0.f);                      // relu(tanh)
    const float r  = tanhf(rpre);
    const float hl = h_last[idx];
    const float h  = g * r + (1.f - g) * hl;
    const float Hg = (g > 0.f) ? 1.f : 0.f;
    const float dg = (1.f - g * g) * Hg;
    const float dr = 1.f - r * r;
    const float delta = r - hl;
    const float a  = 1.f - g;
    const float cg = dg * delta;
    const float cr = dr * g;

    d_av[idx]  = a;
    d_cgv[idx] = cg;
    d_crv[idx] = cr;
    d_hv[idx]  = h;

    out_h[idx]   = h;
    out_ebg[idx] = e_b_g[idx] * a + cg;
    out_ebr[idx] = e_b_r[idx] * a + cr;

    const int cnt = __popc(__ballot_sync(0xffffffffu, g > 0.f));
    if ((threadIdx.x & 31) == 0) scnt[threadIdx.x >> 5] = cnt;
    __syncthreads();
    if (threadIdx.x == 0) {
        int t = 0;
        #pragma unroll
        for (int w = 0; w < 8; w++) t += scnt[w];
        d_cnt[blockIdx.x] = t;
    }
}

// ---------------------------------------------------------------------------
// Paired full-K GEMM for p & o with fused activation epilogue (hidden under
// the trace stream inside k_fused).
// ---------------------------------------------------------------------------
__device__ __forceinline__ void gemm2_body(
    const float* __restrict__ x,
    const float* __restrict__ w_px, const float* __restrict__ w_ph,
    const float* __restrict__ w_ox, const float* __restrict__ w_oh,
    const float* __restrict__ b_p,  const float* __restrict__ b_o,
    float* __restrict__ out, int bx, int tid)
{
    __shared__ float As[16][68];
    __shared__ float Ps[16][68];
    __shared__ float Os[16][68];

    const int j0 = (bx & 7) * 64;
    const int m0 = (bx >> 3) * 64;

    const int lm  = tid & 63;
    const int lk4 = (tid >> 6) << 2;
    const int tx  = tid & 15;
    const int ty  = tid >> 4;

    float accP[4][4], accO[4][4];
    #pragma unroll
    for (int i = 0; i < 4; i++)
        #pragma unroll
        for (int j = 0; j < 4; j++) { accP[i][j] = 0.f; accO[i][j] = 0.f; }

    float4 av = *(const float4*)(x    + (m0 + lm) * 512 + lk4);
    float4 pv = *(const float4*)(w_px + (j0 + lm) * 512 + lk4);
    float4 ov = *(const float4*)(w_ox + (j0 + lm) * 512 + lk4);

    for (int kt = 0; kt < 1024; kt += 16) {
        __syncthreads();
        As[lk4 + 0][lm] = av.x; As[lk4 + 1][lm] = av.y;
        As[lk4 + 2][lm] = av.z; As[lk4 + 3][lm] = av.w;
        Ps[lk4 + 0][lm] = pv.x; Ps[lk4 + 1][lm] = pv.y;
        Ps[lk4 + 2][lm] = pv.z; Ps[lk4 + 3][lm] = pv.w;
        Os[lk4 + 0][lm] = ov.x; Os[lk4 + 1][lm] = ov.y;
        Os[lk4 + 2][lm] = ov.z; Os[lk4 + 3][lm] = ov.w;
        __syncthreads();

        const int kn = kt + 16;
        if (kn < 1024) {
            const int kk2 = (kn < 512) ? kn : (kn - 512);
            const float* An = (kn < 512) ? x    : d_hv;
            const float* Pn = (kn < 512) ? w_px : w_ph;
            const float* On = (kn < 512) ? w_ox : w_oh;
            av = *(const float4*)(An + (m0 + lm) * 512 + kk2 + lk4);
            pv = *(const float4*)(Pn + (j0 + lm) * 512 + kk2 + lk4);
            ov = *(const float4*)(On + (j0 + lm) * 512 + kk2 + lk4);
        }

        #pragma unroll
        for (int kk = 0; kk < 16; kk++) {
            const float4 a = *(const float4*)&As[kk][ty << 2];
            const float4 p = *(const float4*)&Ps[kk][tx << 2];
            const float4 o = *(const float4*)&Os[kk][tx << 2];
            accP[0][0]=fmaf(a.x,p.x,accP[0][0]); accP[0][1]=fmaf(a.x,p.y,accP[0][1]);
            accP[0][2]=fmaf(a.x,p.z,accP[0][2]); accP[0][3]=fmaf(a.x,p.w,accP[0][3]);
            accP[1][0]=fmaf(a.y,p.x,accP[1][0]); accP[1][1]=fmaf(a.y,p.y,accP[1][1]);
            accP[1][2]=fmaf(a.y,p.z,accP[1][2]); accP[1][3]=fmaf(a.y,p.w,accP[1][3]);
            accP[2][0]=fmaf(a.z,p.x,accP[2][0]); accP[2][1]=fmaf(a.z,p.y,accP[2][1]);
            accP[2][2]=fmaf(a.z,p.z,accP[2][2]); accP[2][3]=fmaf(a.z,p.w,accP[2][3]);
            accP[3][0]=fmaf(a.w,p.x,accP[3][0]); accP[3][1]=fmaf(a.w,p.y,accP[3][1]);
            accP[3][2]=fmaf(a.w,p.z,accP[3][2]); accP[3][3]=fmaf(a.w,p.w,accP[3][3]);
            accO[0][0]=fmaf(a.x,o.x,accO[0][0]); accO[0][1]=fmaf(a.x,o.y,accO[0][1]);
            accO[0][2]=fmaf(a.x,o.z,accO[0][2]); accO[0][3]=fmaf(a.x,o.w,accO[0][3]);
            accO[1][0]=fmaf(a.y,o.x,accO[1][0]); accO[1][1]=fmaf(a.y,o.y,accO[1][1]);
            accO[1][2]=fmaf(a.y,o.z,accO[1][2]); accO[1][3]=fmaf(a.y,o.w,accO[1][3]);
            accO[2][0]=fmaf(a.z,o.x,accO[2][0]); accO[2][1]=fmaf(a.z,o.y,accO[2][1]);
            accO[2][2]=fmaf(a.z,o.z,accO[2][2]); accO[2][3]=fmaf(a.z,o.w,accO[2][3]);
            accO[3][0]=fmaf(a.w,o.x,accO[3][0]); accO[3][1]=fmaf(a.w,o.y,accO[3][1]);
            accO[3][2]=fmaf(a.w,o.z,accO[3][2]); accO[3][3]=fmaf(a.w,o.w,accO[3][3]);
        }
    }

    #pragma unroll
    for (int i = 0; i < 4; i++) {
        float4 v;
        #pragma unroll
        for (int j = 0; j < 4; j++) {
            const int jj = j0 + (tx << 2) + j;
            const float pre_p = accP[i][j] + b_p[jj];
            const float pre_o = accO[i][j] + b_o[jj];
            const float pval  = tanhf(pre_p);
            const float oval  = 1.f / (1.f + expf(-pre_o));
            ((float*)&v)[j] = oval * pval;
        }
        *(float4*)(out + (m0 + (ty << 2) + i) * 512 + j0 + (tx << 2)) = v;
    }
}

// Trace row update body (plain cached float4 — streaming hints REGRESSED).
__device__ __forceinline__ void trace_body(
    int idx,
    const float* __restrict__ x,  const float* __restrict__ hl,
    const float* __restrict__ egx, const float* __restrict__ egh,
    const float* __restrict__ erx, const float* __restrict__ erh,
    float* __restrict__ ogx, float* __restrict__ ogh,
    float* __restrict__ orx, float* __restrict__ orh)
{
    const int i   = (idx & 127) << 2;
    const int bj  = idx >> 7;
    const int b   = bj >> 9;

    const float a  = __ldg(&d_av[bj]);
    const float cg = __ldg(&d_cgv[bj]);
    const float cr = __ldg(&d_crv[bj]);

    const float4 xv = *(const float4*)(x  + (b << 9) + i);
    const float4 hv = *(const float4*)(hl + (b << 9) + i);
    const int off = (bj << 9) + i;

    float4 e, t;

    e = *(const float4*)(egx + off);
    t.x = e.x * a + cg * xv.x; t.y = e.y * a + cg * xv.y;
    t.z = e.z * a + cg * xv.z; t.w = e.w * a + cg * xv.w;
    *(float4*)(ogx + off) = t;

    e = *(const float4*)(egh + off);
    t.x = e.x * a + cg * hv.x; t.y = e.y * a + cg * hv.y;
    t.z = e.z * a + cg * hv.z; t.w = e.w * a + cg * hv.w;
    *(float4*)(ogh + off) = t;

    e = *(const float4*)(erx + off);
    t.x = e.x * a + cr * xv.x; t.y = e.y * a + cr * xv.y;
    t.z = e.z * a + cr * xv.z; t.w = e.w * a + cr * xv.w;
    *(float4*)(orx + off) = t;

    e = *(const float4*)(erh + off);
    t.x = e.x * a + cr * hv.x; t.y = e.y * a + cr * hv.y;
    t.z = e.z * a + cr * hv.z; t.w = e.w * a + cr * hv.w;
    *(float4*)(orh + off) = t;
}

// ---------------------------------------------------------------------------
// Launch 3: FUSED kernel.
//   blocks [0, 16)        : paired p/o GEMM, fused activation -> out
//   blocks [16, 16+32768) : HBM-bound trace update
//   block  16+32768       : openings scalar from d_cnt
// ---------------------------------------------------------------------------
__global__ void __launch_bounds__(256) k_fused(
    const float* __restrict__ x,  const float* __restrict__ h_last,
    const float* __restrict__ w_px, const float* __restrict__ w_ph,
    const float* __restrict__ w_ox, const float* __restrict__ w_oh,
    const float* __restrict__ b_p,  const float* __restrict__ b_o,
    const float* __restrict__ egx, const float* __restrict__ egh,
    const float* __restrict__ erx, const float* __restrict__ erh,
    float* __restrict__ ogx, float* __restrict__ ogh,
    float* __restrict__ orx, float* __restrict__ orh,
    float* __restrict__ o_out, float* __restrict__ o_open)
{
    const int bx = blockIdx.x;
    if (bx < GEMM2_BLOCKS) {
        gemm2_body(x, w_px, w_ph, w_ox, w_oh, b_p, b_o, o_out, bx, threadIdx.x);
    } else if (bx < GEMM2_BLOCKS + TRACE_BLOCKS) {
        const int idx = (bx - GEMM2_BLOCKS) * 256 + threadIdx.x;
        trace_body(idx, x, h_last, egx, egh, erx, erh, ogx, ogh, orx, orh);
    } else {
        __shared__ int scnt[256];
        scnt[threadIdx.x] = d_cnt[threadIdx.x];
        __syncthreads();
        for (int st = 128; st > 0; st >>= 1) {
            if (threadIdx.x < st) scnt[threadIdx.x] += scnt[threadIdx.x + st];
            __syncthreads();
        }
        if (threadIdx.x == 0)
            o_open[0] = (float)scnt[0] * (1.f / (float)GATE_ELEMS);
    }
}

// ---------------------------------------------------------------------------
extern "C" void kernel_launch(void* const* d_in, const int* in_sizes, int n_in,
                              void* d_out, int out_size)
{
    const float* x      = (const float*)d_in[0];
    const float* h_last = (const float*)d_in[1];
    const float* w_gx   = (const float*)d_in[2];
    const float* w_gh   = (const float*)d_in[3];
    const float* b_g    = (const float*)d_in[4];
    const float* w_rx   = (const float*)d_in[5];
    const float* w_rh   = (const float*)d_in[6];
    const float* b_r    = (const float*)d_in[7];
    const float* w_px   = (const float*)d_in[8];
    const float* w_ph   = (const float*)d_in[9];
    const float* b_p    = (const float*)d_in[10];
    const float* w_ox   = (const float*)d_in[11];
    const float* w_oh   = (const float*)d_in[12];
    const float* b_o    = (const float*)d_in[13];
    const float* e_w_gx = (const float*)d_in[14];
    const float* e_w_gh = (const float*)d_in[15];
    const float* e_b_g  = (const float*)d_in[16];
    const float* e_w_rx = (const float*)d_in[17];
    const float* e_w_rh = (const float*)d_in[18];
    const float* e_b_r  = (const float*)d_in[19];

    float* out    = (float*)d_out;
    float* o_out  = out;                  // (128,512)
    float* o_h    = out + 65536;          // (128,512)
    float* o_egx  = out + 131072;         // (128,512,512)
    float* o_egh  = out + 33685504;       // (128,512,512)
    float* o_ebg  = out + 67239936;       // (128,512)
    float* o_erx  = out + 67305472;       // (128,512,512)
    float* o_erh  = out + 100859904;      // (128,512,512)
    float* o_ebr  = out + 134414336;      // (128,512)
    float* o_open = out + 134479872;      // scalar

    // g/r pre-activations: 128x128 CTA tiles, split-K=16 -> 128 CTAs
    k_gemm1<<<dim3(8, NSPLIT), 256>>>(x, h_last, w_gx, w_gh, w_rx, w_rh);

    // gate math, h, e_b updates, per-block open counts
    k_gates<<<256, 256>>>(h_last, b_g, b_r, e_b_g, e_b_r, o_h, o_ebg, o_ebr);

    // fused: paired p/o GEMM (+activations) + trace streamer + openings
    k_fused<<<GEMM2_BLOCKS + TRACE_BLOCKS + 1, 256>>>(
        x, h_last, w_px, w_ph, w_ox, w_oh, b_p, b_o,
        e_w_gx, e_w_gh, e_w_rx, e_w_rh,
        o_egx, o_egh, o_erx, o_erh,
        o_out, o_open);
}